// round 4
// baseline (speedup 1.0000x reference)
#include <cuda_runtime.h>
#include <cuda_fp16.h>
#include <cstdint>

// ----------------------------------------------------------------------------
// Linear4bit via fp16 mma.sync (tcgen05 unavailable: PTX target sm_103).
//   out[m,o] = scale*(sum_k x_h[m,k]*wq[o,k]) - scale*zp*rowsum_h[m] + bias[o]
// R4: fp16-ACC HMMA experiment. K=32 sub-chunks accumulate in fp16 (2 chained
//     f16-acc MMAs from zero), promoted into fp32 master accumulators.
//     Tests whether HMMA.F16-acc is double-rate vs F32-acc (measured rt=8).
//   M = 8192, K = 4096, N = 11008.  CTA 128x256, 8 warps, warp tile 64x64.
// ----------------------------------------------------------------------------

static constexpr int M_TOT = 8192;
static constexpr int K_TOT = 4096;
static constexpr int N_TOT = 11008;

static constexpr int BM = 128;
static constexpr int BN = 256;
static constexpr int KC = 64;                    // halves per chunk (128 B row)
static constexpr int NK = K_TOT / KC;            // 64
static constexpr int GRID_M = M_TOT / BM;        // 64
static constexpr int GRID_N = N_TOT / BN;        // 43
static constexpr int NCTAS = GRID_M * GRID_N;    // 2752
static constexpr int NSTAGE = 4;
static constexpr int A_BYTES = BM * KC * 2;      // 16384
static constexpr int B_BYTES = BN * KC * 2;      // 32768
static constexpr int STAGE = A_BYTES + B_BYTES;  // 49152
static constexpr int SMEM_TOTAL = NSTAGE * STAGE;  // 196608

// Scratch (device globals — allocation-free per harness rules)
__device__ __align__(128) __half g_W[(size_t)N_TOT * K_TOT];  // exact fp16 wq
__device__ __align__(128) __half g_X[(size_t)M_TOT * K_TOT];  // fp16(x)
__device__ float g_rowsum[M_TOT];                             // sum_k fp16(x)

// ---------------------------------------------------------------- helpers ---
__device__ __forceinline__ uint32_t smem_u32(const void* p) {
    uint32_t a;
    asm("{ .reg .u64 t; cvta.to.shared.u64 t, %1; cvt.u32.u64 %0, t; }"
        : "=r"(a) : "l"(p));
    return a;
}

__device__ __forceinline__ void cp16(uint32_t dst, const void* src) {
    asm volatile("cp.async.cg.shared.global [%0], [%1], 16;" :: "r"(dst), "l"(src));
}

__device__ __forceinline__ uint32_t pack2(__half a, __half b) {
    return (uint32_t)__half_as_ushort(a) | ((uint32_t)__half_as_ushort(b) << 16);
}

#define LDSM4(r0, r1, r2, r3, addr)                                        \
    asm volatile("ldmatrix.sync.aligned.m8n8.x4.shared.b16 {%0,%1,%2,%3}, [%4];" \
                 : "=r"(r0), "=r"(r1), "=r"(r2), "=r"(r3) : "r"(addr))

// fp16-accumulate MMA: D,C are 2 b32 regs (4 halves), same element mapping
// as the f32 4-reg form (reg0 = row r cols {c,c+1}, reg1 = row r+8).
#define MMA16816H(H, A, B0, B1)                                            \
    asm volatile(                                                          \
        "mma.sync.aligned.m16n8k16.row.col.f16.f16.f16.f16 "               \
        "{%0,%1}, {%2,%3,%4,%5}, {%6,%7}, {%0,%1};"                        \
        : "+r"((H)[0]), "+r"((H)[1])                                       \
        : "r"((A)[0]), "r"((A)[1]), "r"((A)[2]), "r"((A)[3]),              \
          "r"(B0), "r"(B1))

// ------------------------------------------------------------- pre-passes ---
__global__ void dummy_shift() {}

__global__ void __launch_bounds__(256) prep_w(const int* __restrict__ q) {
    const size_t n4 = (size_t)N_TOT * K_TOT / 4;
    const int4* q4 = (const int4*)q;
    uint2* o = (uint2*)g_W;
    for (size_t i = blockIdx.x * blockDim.x + threadIdx.x; i < n4;
         i += (size_t)gridDim.x * blockDim.x) {
        int4 v = q4[i];
        uint2 r;
        r.x = pack2(__int2half_rn(v.x), __int2half_rn(v.y));
        r.y = pack2(__int2half_rn(v.z), __int2half_rn(v.w));
        o[i] = r;
    }
}

// one block (256 thr) per row: convert to fp16 and accumulate rowsum of halves
__global__ void __launch_bounds__(256) prep_x(const float* __restrict__ x) {
    const int row = blockIdx.x;
    const int tid = threadIdx.x;
    const size_t base = (size_t)row * K_TOT;
    const float4* xv = (const float4*)(x + base);
    uint2* o = (uint2*)(g_X + base);
    float s = 0.f;
#pragma unroll
    for (int i = 0; i < 4; i++) {
        float4 v = xv[i * 256 + tid];
        __half h0 = __float2half_rn(v.x), h1 = __float2half_rn(v.y);
        __half h2 = __float2half_rn(v.z), h3 = __float2half_rn(v.w);
        s += __half2float(h0) + __half2float(h1) + __half2float(h2) + __half2float(h3);
        uint2 r;
        r.x = pack2(h0, h1);
        r.y = pack2(h2, h3);
        o[i * 256 + tid] = r;
    }
#pragma unroll
    for (int off = 16; off; off >>= 1) s += __shfl_xor_sync(0xFFFFFFFFu, s, off);
    __shared__ float red[8];
    if ((tid & 31) == 0) red[tid >> 5] = s;
    __syncthreads();
    if (tid == 0) {
        float t = 0.f;
#pragma unroll
        for (int j = 0; j < 8; j++) t += red[j];
        g_rowsum[row] = t;
    }
}

// ------------------------------------------------------------ main kernel ---
// 256 threads fill one 48KB stage: A 128 rows x 8 cols(16B), B 256 rows x 8.
__device__ __forceinline__ void load_stage(uint32_t sdst, int k, int m_base,
                                           int n_base, int tid) {
    const int k0 = k * KC;
#pragma unroll
    for (int i = 0; i < 4; i++) {
        int c = tid + i * 256;
        int row = c >> 3, col = c & 7;
        uint32_t d = sdst + row * 128 + ((col ^ (row & 7)) << 4);
        cp16(d, &g_X[(size_t)(m_base + row) * K_TOT + k0 + col * 8]);
    }
#pragma unroll
    for (int i = 0; i < 8; i++) {
        int c = tid + i * 256;
        int row = c >> 3, col = c & 7;
        uint32_t d = sdst + A_BYTES + row * 128 + ((col ^ (row & 7)) << 4);
        cp16(d, &g_W[(size_t)(n_base + row) * K_TOT + k0 + col * 8]);
    }
}

__global__ void __launch_bounds__(256, 1)
gemm_f16(const float* __restrict__ scale, const float* __restrict__ zp,
         const float* __restrict__ bias, float* __restrict__ out) {
    extern __shared__ char smem[];
    const uint32_t sbase = smem_u32(smem);
    const int tid = threadIdx.x;
    const int lane = tid & 31;
    const int wid = tid >> 5;
    const int wr = wid & 1;   // warp row (M): 2 x 64
    const int wc = wid >> 1;  // warp col (N): 4 x 64

    // raster: groups of 8 M-tiles for L2 reuse of A
    const int per = 8 * GRID_N;  // 344
    const int grp = blockIdx.x / per;
    const int rem = blockIdx.x % per;
    const int m_base = (grp * 8 + (rem & 7)) * BM;
    const int n_base = (rem >> 3) * BN;

    float acc[4][8][4];
#pragma unroll
    for (int a = 0; a < 4; a++)
#pragma unroll
        for (int b = 0; b < 8; b++)
#pragma unroll
            for (int c = 0; c < 4; c++) acc[a][b][c] = 0.f;

    // prologue: fill 3 stages
#pragma unroll
    for (int j = 0; j < NSTAGE - 1; j++) {
        load_stage(sbase + j * STAGE, j, m_base, n_base, tid);
        asm volatile("cp.async.commit_group;" ::: "memory");
    }

    // ldmatrix address invariants
    uint32_t arow128[4], arow7[4];
#pragma unroll
    for (int mt = 0; mt < 4; mt++) {
        int r = wr * 64 + mt * 16 + (lane & 15);
        arow128[mt] = (uint32_t)r * 128u;
        arow7[mt] = (uint32_t)(r & 7);
    }
    const uint32_t akhi = (uint32_t)(lane >> 4);  // 0/1
    uint32_t brow128[4], brow7[4];
#pragma unroll
    for (int p = 0; p < 4; p++) {
        int r = wc * 64 + p * 16 + ((lane >> 4) & 1) * 8 + (lane & 7);
        brow128[p] = (uint32_t)r * 128u;
        brow7[p] = (uint32_t)(r & 7);
    }
    const uint32_t bkhi = (uint32_t)((lane >> 3) & 1);  // 0/1

#pragma unroll 1
    for (int k = 0; k < NK; k++) {
        asm volatile("cp.async.wait_group %0;" :: "n"(NSTAGE - 2) : "memory");
        __syncthreads();
        const uint32_t sa = sbase + (k & (NSTAGE - 1)) * STAGE;
        const uint32_t sb = sa + A_BYTES;

        // two half-chunks of K=32: fp16-acc over 2 MMAs, then promote to fp32
#pragma unroll
        for (int hc = 0; hc < 2; hc++) {
            uint32_t af[2][4][4];
            uint32_t bf[2][4][4];
#pragma unroll
            for (int j = 0; j < 2; j++) {
                const int ks = hc * 2 + j;
#pragma unroll
                for (int mt = 0; mt < 4; mt++) {
                    uint32_t kc16 = (uint32_t)(ks * 2) + akhi;
                    uint32_t ad = sa + arow128[mt] + ((kc16 ^ arow7[mt]) << 4);
                    LDSM4(af[j][mt][0], af[j][mt][1], af[j][mt][2], af[j][mt][3], ad);
                }
#pragma unroll
                for (int p = 0; p < 4; p++) {
                    uint32_t kc16 = (uint32_t)(ks * 2) + bkhi;
                    uint32_t bd = sb + brow128[p] + ((kc16 ^ brow7[p]) << 4);
                    LDSM4(bf[j][p][0], bf[j][p][1], bf[j][p][2], bf[j][p][3], bd);
                }
            }
#pragma unroll
            for (int mt = 0; mt < 4; mt++) {
#pragma unroll
                for (int g = 0; g < 8; g++) {
                    uint32_t h[2] = {0u, 0u};
                    MMA16816H(h, af[0][mt], bf[0][g >> 1][(g & 1) * 2],
                              bf[0][g >> 1][(g & 1) * 2 + 1]);
                    MMA16816H(h, af[1][mt], bf[1][g >> 1][(g & 1) * 2],
                              bf[1][g >> 1][(g & 1) * 2 + 1]);
                    const __half2 p0 = *(const __half2*)&h[0];
                    const __half2 p1 = *(const __half2*)&h[1];
                    acc[mt][g][0] += __low2float(p0);
                    acc[mt][g][1] += __high2float(p0);
                    acc[mt][g][2] += __low2float(p1);
                    acc[mt][g][3] += __high2float(p1);
                }
            }
        }

        const int kn = k + NSTAGE - 1;
        if (kn < NK)
            load_stage(sbase + (kn & (NSTAGE - 1)) * STAGE, kn, m_base, n_base, tid);
        asm volatile("cp.async.commit_group;" ::: "memory");
    }

    // ------------------------------------------------------------ epilogue --
    const float sc = __ldg(scale);
    const float msz = -sc * __ldg(zp);
    const int r0 = m_base + wr * 64 + (lane >> 2);
    float adj[4][2];
#pragma unroll
    for (int mt = 0; mt < 4; mt++)
#pragma unroll
        for (int h = 0; h < 2; h++)
            adj[mt][h] = msz * __ldg(&g_rowsum[r0 + mt * 16 + h * 8]);

#pragma unroll
    for (int mt = 0; mt < 4; mt++) {
        const int r = r0 + mt * 16;
#pragma unroll
        for (int g = 0; g < 8; g++) {
            const int c = n_base + wc * 64 + g * 8 + (lane & 3) * 2;
            const float2 bv = *(const float2*)(bias + c);
            float2 v0, v1;
            v0.x = fmaf(sc, acc[mt][g][0], adj[mt][0] + bv.x);
            v0.y = fmaf(sc, acc[mt][g][1], adj[mt][0] + bv.y);
            v1.x = fmaf(sc, acc[mt][g][2], adj[mt][1] + bv.x);
            v1.y = fmaf(sc, acc[mt][g][3], adj[mt][1] + bv.y);
            *(float2*)(out + (size_t)r * N_TOT + c) = v0;
            *(float2*)(out + (size_t)(r + 8) * N_TOT + c) = v1;
        }
    }
}

// ---------------------------------------------------------------- launch ----
extern "C" void kernel_launch(void* const* d_in, const int* in_sizes, int n_in,
                              void* d_out, int out_size) {
    (void)in_sizes; (void)n_in; (void)out_size;
    const float* x     = (const float*)d_in[0];
    const int*   wq    = (const int*)d_in[1];
    const float* scale = (const float*)d_in[2];
    const float* zp    = (const float*)d_in[3];
    const float* bias  = (const float*)d_in[4];
    float* out = (float*)d_out;

    dummy_shift<<<1, 32>>>();   // phase-shift ncu -s 5 capture onto the GEMM
    prep_w<<<8192, 256>>>(wq);
    prep_x<<<M_TOT, 256>>>(x);

    cudaFuncSetAttribute(gemm_f16, cudaFuncAttributeMaxDynamicSharedMemorySize,
                         SMEM_TOTAL);
    gemm_f16<<<NCTAS, 256, SMEM_TOTAL>>>(scale, zp, bias, out);
}

// round 5
// speedup vs baseline: 1.7014x; 1.7014x over previous
#include <cuda_runtime.h>
#include <cuda_fp16.h>
#include <cstdint>

// ----------------------------------------------------------------------------
// Linear4bit via fp16 mma.sync (tcgen05 unavailable: PTX target sm_103).
//   out[m,o] = scale*(sum_k x_h[m,k]*wq[o,k]) - scale*zp*rowsum_h[m] + bias[o]
// R5: occupancy-2 variant. CTA 128x128, 8 warps (2x4), warp tile 64x32,
//     3-stage 32KB cp.async pipeline (96KB smem/CTA -> 2 CTAs/SM),
//     __launch_bounds__(256,2) caps regs at 128 (64 master regs fit).
//     Goal: overlap per-CTA prologue/epilogue/syncs across resident CTAs.
//   M = 8192, K = 4096, N = 11008.
// ----------------------------------------------------------------------------

static constexpr int M_TOT = 8192;
static constexpr int K_TOT = 4096;
static constexpr int N_TOT = 11008;

static constexpr int BM = 128;
static constexpr int BN = 128;
static constexpr int KC = 64;                    // halves per chunk (128 B row)
static constexpr int NK = K_TOT / KC;            // 64
static constexpr int GRID_M = M_TOT / BM;        // 64
static constexpr int GRID_N = N_TOT / BN;        // 86
static constexpr int NCTAS = GRID_M * GRID_N;    // 5504
static constexpr int NSTAGE = 3;
static constexpr int A_BYTES = BM * KC * 2;      // 16384
static constexpr int B_BYTES = BN * KC * 2;      // 16384
static constexpr int STAGE = A_BYTES + B_BYTES;  // 32768
static constexpr int SMEM_TOTAL = NSTAGE * STAGE;  // 98304 -> 2 CTAs/SM

// Scratch (device globals — allocation-free per harness rules)
__device__ __align__(128) __half g_W[(size_t)N_TOT * K_TOT];  // exact fp16 wq
__device__ __align__(128) __half g_X[(size_t)M_TOT * K_TOT];  // fp16(x)
__device__ float g_rowsum[M_TOT];                             // sum_k fp16(x)

// ---------------------------------------------------------------- helpers ---
__device__ __forceinline__ uint32_t smem_u32(const void* p) {
    uint32_t a;
    asm("{ .reg .u64 t; cvta.to.shared.u64 t, %1; cvt.u32.u64 %0, t; }"
        : "=r"(a) : "l"(p));
    return a;
}

__device__ __forceinline__ void cp16(uint32_t dst, const void* src) {
    asm volatile("cp.async.cg.shared.global [%0], [%1], 16;" :: "r"(dst), "l"(src));
}

__device__ __forceinline__ uint32_t pack2(__half a, __half b) {
    return (uint32_t)__half_as_ushort(a) | ((uint32_t)__half_as_ushort(b) << 16);
}

#define LDSM4(r0, r1, r2, r3, addr)                                        \
    asm volatile("ldmatrix.sync.aligned.m8n8.x4.shared.b16 {%0,%1,%2,%3}, [%4];" \
                 : "=r"(r0), "=r"(r1), "=r"(r2), "=r"(r3) : "r"(addr))

#define MMA16816(C, A, B0, B1)                                             \
    asm volatile(                                                          \
        "mma.sync.aligned.m16n8k16.row.col.f32.f16.f16.f32 "               \
        "{%0,%1,%2,%3}, {%4,%5,%6,%7}, {%8,%9}, {%0,%1,%2,%3};"            \
        : "+f"((C)[0]), "+f"((C)[1]), "+f"((C)[2]), "+f"((C)[3])           \
        : "r"((A)[0]), "r"((A)[1]), "r"((A)[2]), "r"((A)[3]),              \
          "r"(B0), "r"(B1))

// ------------------------------------------------------------- pre-passes ---
__global__ void dummy_shift() {}

// Merged prep: blocks [0, 8192) convert W (grid-stride), blocks [8192, 16384)
// convert one X row each + rowsum.  Overlaps the two bandwidth streams.
__global__ void __launch_bounds__(256) prep_all(const float* __restrict__ x,
                                                const int* __restrict__ q) {
    const int tid = threadIdx.x;
    if (blockIdx.x < 8192) {
        const size_t n4 = (size_t)N_TOT * K_TOT / 4;
        const int4* q4 = (const int4*)q;
        uint2* o = (uint2*)g_W;
        for (size_t i = blockIdx.x * 256 + tid; i < n4; i += (size_t)8192 * 256) {
            int4 v = q4[i];
            uint2 r;
            r.x = pack2(__int2half_rn(v.x), __int2half_rn(v.y));
            r.y = pack2(__int2half_rn(v.z), __int2half_rn(v.w));
            o[i] = r;
        }
    } else {
        const int row = blockIdx.x - 8192;
        const size_t base = (size_t)row * K_TOT;
        const float4* xv = (const float4*)(x + base);
        uint2* o = (uint2*)(g_X + base);
        float s = 0.f;
#pragma unroll
        for (int i = 0; i < 4; i++) {
            float4 v = xv[i * 256 + tid];
            __half h0 = __float2half_rn(v.x), h1 = __float2half_rn(v.y);
            __half h2 = __float2half_rn(v.z), h3 = __float2half_rn(v.w);
            s += __half2float(h0) + __half2float(h1) + __half2float(h2) +
                 __half2float(h3);
            uint2 r;
            r.x = pack2(h0, h1);
            r.y = pack2(h2, h3);
            o[i * 256 + tid] = r;
        }
#pragma unroll
        for (int off = 16; off; off >>= 1) s += __shfl_xor_sync(0xFFFFFFFFu, s, off);
        __shared__ float red[8];
        if ((tid & 31) == 0) red[tid >> 5] = s;
        __syncthreads();
        if (tid == 0) {
            float t = 0.f;
#pragma unroll
            for (int j = 0; j < 8; j++) t += red[j];
            g_rowsum[row] = t;
        }
    }
}

// ------------------------------------------------------------ main kernel ---
// 256 threads fill one 32KB stage: A 128 rows x 8 cols(16B), B 128 rows x 8.
__device__ __forceinline__ void load_stage(uint32_t sdst, int k, int m_base,
                                           int n_base, int tid) {
    const int k0 = k * KC;
#pragma unroll
    for (int i = 0; i < 4; i++) {
        int c = tid + i * 256;
        int row = c >> 3, col = c & 7;
        uint32_t d = sdst + row * 128 + ((col ^ (row & 7)) << 4);
        cp16(d, &g_X[(size_t)(m_base + row) * K_TOT + k0 + col * 8]);
    }
#pragma unroll
    for (int i = 0; i < 4; i++) {
        int c = tid + i * 256;
        int row = c >> 3, col = c & 7;
        uint32_t d = sdst + A_BYTES + row * 128 + ((col ^ (row & 7)) << 4);
        cp16(d, &g_W[(size_t)(n_base + row) * K_TOT + k0 + col * 8]);
    }
}

__global__ void __launch_bounds__(256, 2)
gemm_f16(const float* __restrict__ scale, const float* __restrict__ zp,
         const float* __restrict__ bias, float* __restrict__ out) {
    extern __shared__ char smem[];
    const uint32_t sbase = smem_u32(smem);
    const int tid = threadIdx.x;
    const int lane = tid & 31;
    const int wid = tid >> 5;
    const int wr = wid & 1;   // warp row (M): 2 x 64
    const int wc = wid >> 1;  // warp col (N): 4 x 32

    // raster: groups of 8 M-tiles -> B slice of the group (~90MB) fits L2
    const int per = 8 * GRID_N;  // 688
    const int grp = blockIdx.x / per;
    const int rem = blockIdx.x % per;
    const int m_base = (grp * 8 + (rem & 7)) * BM;
    const int n_base = (rem >> 3) * BN;

    float acc[4][4][4];
#pragma unroll
    for (int a = 0; a < 4; a++)
#pragma unroll
        for (int b = 0; b < 4; b++)
#pragma unroll
            for (int c = 0; c < 4; c++) acc[a][b][c] = 0.f;

    // prologue: fill 2 stages
    load_stage(sbase, 0, m_base, n_base, tid);
    asm volatile("cp.async.commit_group;" ::: "memory");
    load_stage(sbase + STAGE, 1, m_base, n_base, tid);
    asm volatile("cp.async.commit_group;" ::: "memory");

    // ldmatrix address invariants
    uint32_t arow128[4], arow7[4];
#pragma unroll
    for (int mt = 0; mt < 4; mt++) {
        int r = wr * 64 + mt * 16 + (lane & 15);
        arow128[mt] = (uint32_t)r * 128u;
        arow7[mt] = (uint32_t)(r & 7);
    }
    const uint32_t akhi = (uint32_t)(lane >> 4);  // 0/1
    uint32_t brow128[2], brow7[2];
#pragma unroll
    for (int p = 0; p < 2; p++) {
        int r = wc * 32 + p * 16 + ((lane >> 4) & 1) * 8 + (lane & 7);
        brow128[p] = (uint32_t)r * 128u;
        brow7[p] = (uint32_t)(r & 7);
    }
    const uint32_t bkhi = (uint32_t)((lane >> 3) & 1);  // 0/1

    int s = 0;   // stage of chunk k
    int pf = 2;  // stage of chunk k+2
#pragma unroll 1
    for (int k = 0; k < NK; k++) {
        asm volatile("cp.async.wait_group 1;" ::: "memory");
        __syncthreads();

        // prefetch k+2 first so it overlaps this chunk's MMAs
        const int kn = k + 2;
        if (kn < NK) load_stage(sbase + pf * STAGE, kn, m_base, n_base, tid);
        asm volatile("cp.async.commit_group;" ::: "memory");

        const uint32_t sa = sbase + s * STAGE;
        const uint32_t sb = sa + A_BYTES;
#pragma unroll
        for (int ks = 0; ks < 4; ks++) {
            uint32_t af[4][4];
#pragma unroll
            for (int mt = 0; mt < 4; mt++) {
                uint32_t kc16 = (uint32_t)(ks * 2) + akhi;
                uint32_t ad = sa + arow128[mt] + ((kc16 ^ arow7[mt]) << 4);
                LDSM4(af[mt][0], af[mt][1], af[mt][2], af[mt][3], ad);
            }
            uint32_t bf[2][4];
#pragma unroll
            for (int p = 0; p < 2; p++) {
                uint32_t kc16 = (uint32_t)(ks * 2) + bkhi;
                uint32_t bd = sb + brow128[p] + ((kc16 ^ brow7[p]) << 4);
                LDSM4(bf[p][0], bf[p][1], bf[p][2], bf[p][3], bd);
            }
#pragma unroll
            for (int mt = 0; mt < 4; mt++)
#pragma unroll
                for (int g = 0; g < 4; g++)
                    MMA16816(acc[mt][g], af[mt], bf[g >> 1][(g & 1) * 2],
                             bf[g >> 1][(g & 1) * 2 + 1]);
        }

        s = (s == 2) ? 0 : s + 1;
        pf = (pf == 2) ? 0 : pf + 1;
    }

    // ------------------------------------------------------------ epilogue --
    const float sc = __ldg(scale);
    const float msz = -sc * __ldg(zp);
    const int r0 = m_base + wr * 64 + (lane >> 2);
    float adj[4][2];
#pragma unroll
    for (int mt = 0; mt < 4; mt++)
#pragma unroll
        for (int h = 0; h < 2; h++)
            adj[mt][h] = msz * __ldg(&g_rowsum[r0 + mt * 16 + h * 8]);

#pragma unroll
    for (int mt = 0; mt < 4; mt++) {
        const int r = r0 + mt * 16;
#pragma unroll
        for (int g = 0; g < 4; g++) {
            const int c = n_base + wc * 32 + g * 8 + (lane & 3) * 2;
            const float2 bv = *(const float2*)(bias + c);
            float2 v0, v1;
            v0.x = fmaf(sc, acc[mt][g][0], adj[mt][0] + bv.x);
            v0.y = fmaf(sc, acc[mt][g][1], adj[mt][0] + bv.y);
            v1.x = fmaf(sc, acc[mt][g][2], adj[mt][1] + bv.x);
            v1.y = fmaf(sc, acc[mt][g][3], adj[mt][1] + bv.y);
            *(float2*)(out + (size_t)r * N_TOT + c) = v0;
            *(float2*)(out + (size_t)(r + 8) * N_TOT + c) = v1;
        }
    }
}

// ---------------------------------------------------------------- launch ----
extern "C" void kernel_launch(void* const* d_in, const int* in_sizes, int n_in,
                              void* d_out, int out_size) {
    (void)in_sizes; (void)n_in; (void)out_size;
    const float* x     = (const float*)d_in[0];
    const int*   wq    = (const int*)d_in[1];
    const float* scale = (const float*)d_in[2];
    const float* zp    = (const float*)d_in[3];
    const float* bias  = (const float*)d_in[4];
    float* out = (float*)d_out;

    dummy_shift<<<1, 32>>>();   // phase-shift ncu -s 5 capture onto the GEMM
    prep_all<<<16384, 256>>>(x, wq);

    cudaFuncSetAttribute(gemm_f16, cudaFuncAttributeMaxDynamicSharedMemorySize,
                         SMEM_TOTAL);
    gemm_f16<<<NCTAS, 256, SMEM_TOTAL>>>(scale, zp, bias, out);
}